// round 1
// baseline (speedup 1.0000x reference)
#include <cuda_runtime.h>

#define EMBED   1024
#define HEADS   16
#define HD      64
#define BATCH   8
#define SEQ     1024
#define ROWS    (BATCH * SEQ)      // 8192
#define QKV_N   (3 * EMBED)        // 3072
#define SCALE_F 0.125f             // 64^-0.5

// Scratch (device globals: allocation-free per harness rules)
__device__ float g_q[BATCH * HEADS * SEQ * HD];      // 33.5 MB, pre-scaled by SCALE
__device__ float g_k[BATCH * HEADS * SEQ * HD];
__device__ float g_v[BATCH * HEADS * SEQ * HD];
__device__ float g_attn[ROWS * EMBED];               // [B*N, E] attention output

// ---------------------------------------------------------------------------
// GEMM: C = A @ B^T + bias.  A [M,K] row-major, B [N,K] row-major.
// Block tile 128x128, K-tile 8, 256 threads, 8x8 per-thread micro-tile.
// MODE 0: A = x (param), epilogue scatters into g_q/g_k/g_v [B,H,N,D]
// MODE 1: A = g_attn (internal), epilogue writes C (= d_out) row-major
// ---------------------------------------------------------------------------
template <int MODE>
__global__ __launch_bounds__(256)
void gemm_abT(const float* __restrict__ A, const float* __restrict__ B,
              const float* __restrict__ bias, float* __restrict__ C,
              int N, int K)
{
    __shared__ float As[8][128];
    __shared__ float Bs[8][128];

    const int tid = threadIdx.x;
    const int m0  = blockIdx.y * 128;
    const int n0  = blockIdx.x * 128;
    const int ty  = tid >> 4;        // 0..15 -> row group
    const int tx  = tid & 15;        // 0..15 -> col group

    const int lr = tid >> 1;         // 0..127: tile row to load
    const int ls = (tid & 1) * 4;    // 0 or 4: k-segment

    const float* Aeff = (MODE == 1) ? g_attn : A;
    const float* Aptr = Aeff + (m0 + lr) * K + ls;
    const float* Bptr = B    + (n0 + lr) * K + ls;

    float acc[8][8];
#pragma unroll
    for (int i = 0; i < 8; i++)
#pragma unroll
        for (int j = 0; j < 8; j++) acc[i][j] = 0.f;

    for (int k0 = 0; k0 < K; k0 += 8) {
        float4 av = *(const float4*)(Aptr + k0);
        float4 bv = *(const float4*)(Bptr + k0);
        As[ls + 0][lr] = av.x; As[ls + 1][lr] = av.y;
        As[ls + 2][lr] = av.z; As[ls + 3][lr] = av.w;
        Bs[ls + 0][lr] = bv.x; Bs[ls + 1][lr] = bv.y;
        Bs[ls + 2][lr] = bv.z; Bs[ls + 3][lr] = bv.w;
        __syncthreads();

#pragma unroll
        for (int k = 0; k < 8; k++) {
            float a[8], b[8];
            *(float4*)(a)     = *(const float4*)&As[k][ty * 8];
            *(float4*)(a + 4) = *(const float4*)&As[k][ty * 8 + 4];
            *(float4*)(b)     = *(const float4*)&Bs[k][tx * 8];
            *(float4*)(b + 4) = *(const float4*)&Bs[k][tx * 8 + 4];
#pragma unroll
            for (int i = 0; i < 8; i++)
#pragma unroll
                for (int j = 0; j < 8; j++)
                    acc[i][j] += a[i] * b[j];
        }
        __syncthreads();
    }

#pragma unroll
    for (int i = 0; i < 8; i++) {
        const int r = m0 + ty * 8 + i;
#pragma unroll
        for (int j = 0; j < 8; j++) {
            const int c = n0 + tx * 8 + j;
            float v = acc[i][j] + bias[c];
            if (MODE == 0) {
                // c = t*1024 + h*64 + d ;  r = b*1024 + n
                const int b_  = r >> 10, n = r & 1023;
                const int t   = c >> 10, rem = c & 1023;
                const int h   = rem >> 6, d = rem & 63;
                const int idx = (((b_ * HEADS + h) * SEQ) + n) * HD + d;
                if (t == 0)      g_q[idx] = v * SCALE_F;
                else if (t == 1) g_k[idx] = v;
                else             g_v[idx] = v;
            } else {
                C[r * N + c] = v;
            }
        }
    }
}

// ---------------------------------------------------------------------------
// Flash attention: grid (B*H, SEQ/128), 128 threads; 1 thread = 1 query row.
// K/V staged in 64x64 smem tiles; online softmax per 16-key chunk.
// Q is pre-scaled by SCALE. Writes g_attn[b*SEQ+n][h*64+d].
// ---------------------------------------------------------------------------
__global__ __launch_bounds__(128)
void attn_kernel()
{
    __shared__ float Ks[64][64];
    __shared__ float Vs[64][64];

    const int bh  = blockIdx.x;                 // 0..127
    const int tid = threadIdx.x;
    const int q   = blockIdx.y * 128 + tid;     // token index

    const float* qp = g_q + (bh * SEQ + q) * HD;
    float qr[64];
#pragma unroll
    for (int i = 0; i < 16; i++)
        *(float4*)&qr[i * 4] = *(const float4*)(qp + i * 4);

    float o[64];
#pragma unroll
    for (int d = 0; d < 64; d++) o[d] = 0.f;
    float mrun = -1e30f, lrun = 0.f;

    const float* Kbase = g_k + bh * SEQ * HD;
    const float* Vbase = g_v + bh * SEQ * HD;

    for (int kt = 0; kt < SEQ; kt += 64) {
#pragma unroll
        for (int i = 0; i < 8; i++) {
            const int f4  = i * 128 + tid;      // 0..1023 float4 slots
            const int row = f4 >> 4;
            const int c4  = (f4 & 15) * 4;
            *(float4*)&Ks[row][c4] = *(const float4*)(Kbase + (kt + row) * HD + c4);
            *(float4*)&Vs[row][c4] = *(const float4*)(Vbase + (kt + row) * HD + c4);
        }
        __syncthreads();

#pragma unroll
        for (int jc = 0; jc < 64; jc += 16) {
            float s[16];
#pragma unroll
            for (int j = 0; j < 16; j++) {
                float a0 = 0.f, a1 = 0.f;
#pragma unroll
                for (int d4 = 0; d4 < 64; d4 += 8) {
                    float4 k0 = *(const float4*)&Ks[jc + j][d4];
                    float4 k1 = *(const float4*)&Ks[jc + j][d4 + 4];
                    a0 += qr[d4 + 0] * k0.x + qr[d4 + 1] * k0.y
                        + qr[d4 + 2] * k0.z + qr[d4 + 3] * k0.w;
                    a1 += qr[d4 + 4] * k1.x + qr[d4 + 5] * k1.y
                        + qr[d4 + 6] * k1.z + qr[d4 + 7] * k1.w;
                }
                s[j] = a0 + a1;
            }
            float cmax = s[0];
#pragma unroll
            for (int j = 1; j < 16; j++) cmax = fmaxf(cmax, s[j]);
            const float mnew = fmaxf(mrun, cmax);
            const float corr = __expf(mrun - mnew);
            lrun *= corr;
#pragma unroll
            for (int d = 0; d < 64; d++) o[d] *= corr;
#pragma unroll
            for (int j = 0; j < 16; j++) {
                const float p = __expf(s[j] - mnew);
                lrun += p;
#pragma unroll
                for (int d4 = 0; d4 < 64; d4 += 4) {
                    float4 vv = *(const float4*)&Vs[jc + j][d4];
                    o[d4 + 0] += p * vv.x;
                    o[d4 + 1] += p * vv.y;
                    o[d4 + 2] += p * vv.z;
                    o[d4 + 3] += p * vv.w;
                }
            }
            mrun = mnew;
        }
        __syncthreads();
    }

    const float inv = 1.f / lrun;
    const int b_ = bh >> 4, h = bh & 15;
    float* op = g_attn + (b_ * SEQ + q) * EMBED + h * HD;
#pragma unroll
    for (int i = 0; i < 16; i++) {
        float4 w;
        w.x = o[i * 4 + 0] * inv;
        w.y = o[i * 4 + 1] * inv;
        w.z = o[i * 4 + 2] * inv;
        w.w = o[i * 4 + 3] * inv;
        *(float4*)(op + i * 4) = w;
    }
}

// ---------------------------------------------------------------------------
extern "C" void kernel_launch(void* const* d_in, const int* in_sizes, int n_in,
                              void* d_out, int out_size)
{
    (void)in_sizes; (void)n_in; (void)out_size;
    const float* x      = (const float*)d_in[0];
    const float* w_qkv  = (const float*)d_in[1];
    const float* b_qkv  = (const float*)d_in[2];
    const float* w_proj = (const float*)d_in[3];
    const float* b_proj = (const float*)d_in[4];
    float* out = (float*)d_out;

    // QKV projection + scatter into [B,H,N,D] (Q pre-scaled)
    gemm_abT<0><<<dim3(QKV_N / 128, ROWS / 128), 256>>>(x, w_qkv, b_qkv, nullptr,
                                                        QKV_N, EMBED);
    // Flash attention
    attn_kernel<<<dim3(BATCH * HEADS, SEQ / 128), 128>>>();
    // Output projection
    gemm_abT<1><<<dim3(EMBED / 128, ROWS / 128), 256>>>(nullptr, w_proj, b_proj, out,
                                                        EMBED, EMBED);
}

// round 3
// speedup vs baseline: 1.9840x; 1.9840x over previous
#include <cuda_runtime.h>
#include <cuda_bf16.h>
#include <cstdint>

#define EMBED   1024
#define HEADS   16
#define HD      64
#define BATCH   8
#define SEQ     1024
#define ROWS    8192
#define QKV_N   3072
#define KDIM    1024
#define LOG2E   1.4426950408889634f
#define QSCALE  (0.125f * LOG2E)          // fold 1/sqrt(64) and log2(e) into Q

// ---------------- scratch (device globals; allocation-free) ----------------
__device__ __align__(1024) __nv_bfloat16 g_xh[ROWS * EMBED];
__device__ __align__(1024) __nv_bfloat16 g_xl[ROWS * EMBED];
__device__ __align__(1024) __nv_bfloat16 g_wqh[QKV_N * EMBED];
__device__ __align__(1024) __nv_bfloat16 g_wql[QKV_N * EMBED];
__device__ __align__(1024) __nv_bfloat16 g_wph[EMBED * EMBED];
__device__ __align__(1024) __nv_bfloat16 g_wpl[EMBED * EMBED];
__device__ __align__(1024) float g_q[BATCH * HEADS * SEQ * HD];   // pre-scaled by QSCALE
__device__ __align__(1024) float g_k[BATCH * HEADS * SEQ * HD];
__device__ __align__(1024) float g_v[BATCH * HEADS * SEQ * HD];
__device__ __align__(1024) __nv_bfloat16 g_ah[ROWS * EMBED];      // attention out hi
__device__ __align__(1024) __nv_bfloat16 g_al[ROWS * EMBED];      // attention out lo

// ---------------- helpers ----------------
__device__ __forceinline__ uint32_t smem_u32(const void* p) {
    uint32_t a;
    asm("{ .reg .u64 t; cvta.to.shared.u64 t, %1; cvt.u32.u64 %0, t; }" : "=r"(a) : "l"(p));
    return a;
}
__device__ __forceinline__ float ex2f(float x) {
    float y; asm("ex2.approx.ftz.f32 %0, %1;" : "=f"(y) : "f"(x)); return y;
}
__device__ __forceinline__ uint32_t sw128(uint32_t o) { return o ^ ((o >> 3) & 0x70); }

#define CP_ASYNC(dst, src) \
    asm volatile("cp.async.cg.shared.global [%0], [%1], 16;" :: "r"(dst), "l"(src) : "memory")
#define CP_COMMIT() asm volatile("cp.async.commit_group;" ::: "memory")
#define CP_WAIT1()  asm volatile("cp.async.wait_group 1;" ::: "memory")
#define CP_WAIT0()  asm volatile("cp.async.wait_group 0;" ::: "memory")

__device__ __forceinline__ void ldsm4(uint32_t r[4], uint32_t addr) {
    asm volatile("ldmatrix.sync.aligned.m8n8.x4.shared.b16 {%0,%1,%2,%3}, [%4];"
                 : "=r"(r[0]), "=r"(r[1]), "=r"(r[2]), "=r"(r[3]) : "r"(addr));
}
__device__ __forceinline__ void mma_bf16(float c[4], const uint32_t a[4],
                                         uint32_t b0, uint32_t b1) {
    asm volatile(
        "mma.sync.aligned.m16n8k16.row.col.f32.bf16.bf16.f32 "
        "{%0,%1,%2,%3}, {%4,%5,%6,%7}, {%8,%9}, {%0,%1,%2,%3};"
        : "+f"(c[0]), "+f"(c[1]), "+f"(c[2]), "+f"(c[3])
        : "r"(a[0]), "r"(a[1]), "r"(a[2]), "r"(a[3]), "r"(b0), "r"(b1));
}

// packed fp32x2 (base sm_100 ISA, no 'a' suffix needed)
__device__ __forceinline__ uint64_t fma2(uint64_t a, uint64_t b, uint64_t c) {
    uint64_t d; asm("fma.rn.f32x2 %0, %1, %2, %3;" : "=l"(d) : "l"(a), "l"(b), "l"(c));
    return d;
}
__device__ __forceinline__ uint64_t add2(uint64_t a, uint64_t b) {
    uint64_t d; asm("add.rn.f32x2 %0, %1, %2;" : "=l"(d) : "l"(a), "l"(b));
    return d;
}
__device__ __forceinline__ uint64_t mul2(uint64_t a, uint64_t b) {
    uint64_t d; asm("mul.rn.f32x2 %0, %1, %2;" : "=l"(d) : "l"(a), "l"(b));
    return d;
}
__device__ __forceinline__ uint64_t pack2(float x, float y) {
    uint64_t r; asm("mov.b64 %0, {%1, %2};" : "=l"(r) : "f"(x), "f"(y));
    return r;
}
__device__ __forceinline__ float2 unpack2(uint64_t v) {
    float x, y; asm("mov.b64 {%0, %1}, %2;" : "=f"(x), "=f"(y) : "l"(v));
    return make_float2(x, y);
}

// ---------------- fp32 -> bf16 hi/lo split ----------------
template <int T>
__global__ __launch_bounds__(256)
void split_k(const float* __restrict__ src, int n8)
{
    __nv_bfloat16* h = (T == 0) ? g_xh : (T == 1) ? g_wqh : g_wph;
    __nv_bfloat16* l = (T == 0) ? g_xl : (T == 1) ? g_wql : g_wpl;
    int i = blockIdx.x * 256 + threadIdx.x;
    if (i >= n8) return;
    float4 a = ((const float4*)src)[i * 2];
    float4 b = ((const float4*)src)[i * 2 + 1];
    float v[8] = {a.x, a.y, a.z, a.w, b.x, b.y, b.z, b.w};
    __nv_bfloat16 hb[8], lb[8];
#pragma unroll
    for (int j = 0; j < 8; j++) {
        hb[j] = __float2bfloat16(v[j]);
        lb[j] = __float2bfloat16(v[j] - __bfloat162float(hb[j]));
    }
    ((uint4*)h)[i] = *(uint4*)hb;
    ((uint4*)l)[i] = *(uint4*)lb;
}

// ---------------- mma.sync split-bf16 GEMM: C = A @ B^T + bias ----------------
// 128x128 block tile, K-tile 64, 256 threads (8 warps as 4m x 2n, warp = 32m x 64n),
// cp.async double-buffered, SW128-swizzled smem (128B rows).
// MODE 0: A=x, B=w_qkv  -> scatter q/k/v (q pre-scaled by QSCALE)
// MODE 1: A=attn out,    B=w_proj -> Cout row-major
#define STG_BYTES 65536            // Ah,Al,Bh,Bl = 4 x 16KB per stage
#define SMEM_BYTES (2 * STG_BYTES)

template <int MODE>
__global__ __launch_bounds__(256)
void gemm_mma(const float* __restrict__ bias, float* __restrict__ Cout)
{
    extern __shared__ char smem[];
    const uint32_t sb = smem_u32(smem);
    const int tid = threadIdx.x;
    const int lane = tid & 31;
    const int wid  = tid >> 5;
    const int warp_m = wid & 3;            // 0..3  -> 32-row band
    const int warp_n = wid >> 2;           // 0..1  -> 64-col band
    const int m0 = blockIdx.y * 128;
    const int n0 = blockIdx.x * 128;

    const __nv_bfloat16* Ah = (MODE == 0) ? g_xh  : g_ah;
    const __nv_bfloat16* Al = (MODE == 0) ? g_xl  : g_al;
    const __nv_bfloat16* Bh = (MODE == 0) ? g_wqh : g_wph;
    const __nv_bfloat16* Bl = (MODE == 0) ? g_wql : g_wpl;

    // loader mapping: thread covers seg (tid&7), rows r0 + u*32
    const int r0  = tid >> 3;              // 0..31
    const int seg = tid & 7;               // 16B segment within 128B row

    auto issue = [&](int stage, int kt) {
        const uint32_t s0 = sb + stage * STG_BYTES;
#pragma unroll
        for (int u = 0; u < 4; u++) {
            const int row = r0 + u * 32;
            const uint32_t so = sw128((uint32_t)(row * 128 + seg * 16));
            const int ae = (m0 + row) * KDIM + kt + seg * 8;
            const int be = (n0 + row) * KDIM + kt + seg * 8;
            CP_ASYNC(s0 +         so, (const char*)(Ah + ae));
            CP_ASYNC(s0 + 16384 + so, (const char*)(Al + ae));
            CP_ASYNC(s0 + 32768 + so, (const char*)(Bh + be));
            CP_ASYNC(s0 + 49152 + so, (const char*)(Bl + be));
        }
    };

    float c[2][8][4];
#pragma unroll
    for (int mt = 0; mt < 2; mt++)
#pragma unroll
        for (int nt = 0; nt < 8; nt++)
#pragma unroll
            for (int j = 0; j < 4; j++) c[mt][nt][j] = 0.f;

    issue(0, 0);
    CP_COMMIT();

    const int NIT = KDIM / 64;             // 16
    for (int it = 0; it < NIT; it++) {
        const int s = it & 1;
        if (it + 1 < NIT) { issue(s ^ 1, (it + 1) * 64); CP_COMMIT(); CP_WAIT1(); }
        else              { CP_WAIT0(); }
        __syncthreads();

        const uint32_t sA_h = sb + s * STG_BYTES;
        const uint32_t sA_l = sA_h + 16384;
        const uint32_t sB_h = sA_h + 32768;
        const uint32_t sB_l = sA_h + 49152;

#pragma unroll
        for (int ks = 0; ks < 4; ks++) {
            // A fragments (hi, lo): 2 m16 tiles
            uint32_t ah[2][4], al[2][4];
#pragma unroll
            for (int mt = 0; mt < 2; mt++) {
                const int arow = warp_m * 32 + mt * 16 + (lane & 7) + ((lane >> 3) & 1) * 8;
                const int aseg = ks * 2 + (lane >> 4);
                const uint32_t off = sw128((uint32_t)(arow * 128 + aseg * 16));
                ldsm4(ah[mt], sA_h + off);
                ldsm4(al[mt], sA_l + off);
            }
            // B fragments (hi, lo): 8 n8 tiles as 4 pairs
            uint32_t bh[8][2], bl[8][2];
#pragma unroll
            for (int p = 0; p < 4; p++) {
                const int brow = warp_n * 64 + p * 16 + (lane >> 4) * 8 + (lane & 7);
                const int bseg = ks * 2 + ((lane >> 3) & 1);
                const uint32_t off = sw128((uint32_t)(brow * 128 + bseg * 16));
                uint32_t rh[4], rl[4];
                ldsm4(rh, sB_h + off);
                ldsm4(rl, sB_l + off);
                bh[2*p][0] = rh[0]; bh[2*p][1] = rh[1];
                bh[2*p+1][0] = rh[2]; bh[2*p+1][1] = rh[3];
                bl[2*p][0] = rl[0]; bl[2*p][1] = rl[1];
                bl[2*p+1][0] = rl[2]; bl[2*p+1][1] = rl[3];
            }
#pragma unroll
            for (int mt = 0; mt < 2; mt++)
#pragma unroll
                for (int nt = 0; nt < 8; nt++) {
                    mma_bf16(c[mt][nt], ah[mt], bh[nt][0], bh[nt][1]);
                    mma_bf16(c[mt][nt], ah[mt], bl[nt][0], bl[nt][1]);
                    mma_bf16(c[mt][nt], al[mt], bh[nt][0], bh[nt][1]);
                }
        }
        __syncthreads();
    }

    // epilogue: c0,c1 -> (row g, col 2t..2t+1); c2,c3 -> row g+8
    const int g = lane >> 2, t = lane & 3;
#pragma unroll
    for (int mt = 0; mt < 2; mt++) {
#pragma unroll
        for (int nt = 0; nt < 8; nt++) {
            const int col = n0 + warp_n * 64 + nt * 8 + t * 2;
            const float b0 = __ldg(&bias[col]), b1 = __ldg(&bias[col + 1]);
#pragma unroll
            for (int half = 0; half < 2; half++) {
                const int row = m0 + warp_m * 32 + mt * 16 + g + half * 8;
                float v0 = c[mt][nt][half * 2 + 0] + b0;
                float v1 = c[mt][nt][half * 2 + 1] + b1;
                if (MODE == 0) {
                    const int b_ = row >> 10, n = row & 1023;
                    const int ty = col >> 10, rem = col & 1023;
                    const int h  = rem >> 6, d = rem & 63;
                    float* dst = ((ty == 0) ? g_q : (ty == 1) ? g_k : g_v)
                               + (((b_ * HEADS + h) * SEQ) + n) * HD + d;
                    if (ty == 0) { v0 *= QSCALE; v1 *= QSCALE; }
                    *(float2*)dst = make_float2(v0, v1);
                } else {
                    *(float2*)(Cout + row * EMBED + col) = make_float2(v0, v1);
                }
            }
        }
    }
}

// ---------------- flash attention (packed f32x2, exp2 domain) ----------------
__global__ __launch_bounds__(128)
void attn_kernel()
{
    __shared__ float Ks[64][64];
    __shared__ float Vs[64][64];

    const int bh  = blockIdx.x;
    const int tid = threadIdx.x;
    const int q   = blockIdx.y * 128 + tid;

    uint64_t q2[32];
    {
        const ulonglong2* qp = (const ulonglong2*)(g_q + (bh * SEQ + q) * HD);
#pragma unroll
        for (int i = 0; i < 16; i++) { ulonglong2 v = qp[i]; q2[2*i] = v.x; q2[2*i+1] = v.y; }
    }
    uint64_t o2[32];
#pragma unroll
    for (int i = 0; i < 32; i++) o2[i] = 0ull;
    float mrun = -1e30f, lrun = 0.f;

    const float* Kbase = g_k + bh * SEQ * HD;
    const float* Vbase = g_v + bh * SEQ * HD;

    for (int kt = 0; kt < SEQ; kt += 64) {
#pragma unroll
        for (int i = 0; i < 8; i++) {
            const int f4  = i * 128 + tid;
            const int row = f4 >> 4;
            const int c4  = (f4 & 15) * 4;
            *(float4*)&Ks[row][c4] = *(const float4*)(Kbase + (kt + row) * HD + c4);
            *(float4*)&Vs[row][c4] = *(const float4*)(Vbase + (kt + row) * HD + c4);
        }
        __syncthreads();

#pragma unroll
        for (int jc = 0; jc < 4; jc++) {
            float s[16];
#pragma unroll
            for (int j = 0; j < 16; j++) {
                const ulonglong2* kr = (const ulonglong2*)&Ks[jc * 16 + j][0];
                uint64_t a0 = 0ull, a1 = 0ull, a2 = 0ull, a3 = 0ull;
#pragma unroll
                for (int d8 = 0; d8 < 8; d8++) {
                    ulonglong2 kA = kr[d8 * 2];
                    ulonglong2 kB = kr[d8 * 2 + 1];
                    a0 = fma2(q2[d8 * 4 + 0], kA.x, a0);
                    a1 = fma2(q2[d8 * 4 + 1], kA.y, a1);
                    a2 = fma2(q2[d8 * 4 + 2], kB.x, a2);
                    a3 = fma2(q2[d8 * 4 + 3], kB.y, a3);
                }
                a0 = add2(a0, a1); a2 = add2(a2, a3); a0 = add2(a0, a2);
                float2 r = unpack2(a0);
                s[j] = r.x + r.y;
            }
            float cmax = s[0];
#pragma unroll
            for (int j = 1; j < 16; j++) cmax = fmaxf(cmax, s[j]);
            if (cmax > mrun) {
                const float corr = ex2f(mrun - cmax);
                lrun *= corr;
                const uint64_t corr2 = pack2(corr, corr);
#pragma unroll
                for (int i = 0; i < 32; i++) o2[i] = mul2(corr2, o2[i]);
                mrun = cmax;
            }
#pragma unroll
            for (int j = 0; j < 16; j++) {
                const float p = ex2f(s[j] - mrun);
                lrun += p;
                const uint64_t pp = pack2(p, p);
                const ulonglong2* vr = (const ulonglong2*)&Vs[jc * 16 + j][0];
#pragma unroll
                for (int d8 = 0; d8 < 8; d8++) {
                    ulonglong2 vA = vr[d8 * 2];
                    ulonglong2 vB = vr[d8 * 2 + 1];
                    o2[d8 * 4 + 0] = fma2(pp, vA.x, o2[d8 * 4 + 0]);
                    o2[d8 * 4 + 1] = fma2(pp, vA.y, o2[d8 * 4 + 1]);
                    o2[d8 * 4 + 2] = fma2(pp, vB.x, o2[d8 * 4 + 2]);
                    o2[d8 * 4 + 3] = fma2(pp, vB.y, o2[d8 * 4 + 3]);
                }
            }
        }
        __syncthreads();
    }

    const float inv = 1.f / lrun;
    const int b_ = bh >> 4, h = bh & 15;
    const int base = (b_ * SEQ + q) * EMBED + h * HD;
#pragma unroll
    for (int gr = 0; gr < 8; gr++) {
        __nv_bfloat16 hb[8], lb[8];
#pragma unroll
        for (int j2 = 0; j2 < 4; j2++) {
            float2 v = unpack2(o2[gr * 4 + j2]);
            v.x *= inv; v.y *= inv;
            hb[j2*2]   = __float2bfloat16(v.x);
            lb[j2*2]   = __float2bfloat16(v.x - __bfloat162float(hb[j2*2]));
            hb[j2*2+1] = __float2bfloat16(v.y);
            lb[j2*2+1] = __float2bfloat16(v.y - __bfloat162float(hb[j2*2+1]));
        }
        *(uint4*)(g_ah + base + gr * 8) = *(uint4*)hb;
        *(uint4*)(g_al + base + gr * 8) = *(uint4*)lb;
    }
}

// ---------------------------------------------------------------------------
extern "C" void kernel_launch(void* const* d_in, const int* in_sizes, int n_in,
                              void* d_out, int out_size)
{
    (void)in_sizes; (void)n_in; (void)out_size;
    const float* x      = (const float*)d_in[0];
    const float* w_qkv  = (const float*)d_in[1];
    const float* b_qkv  = (const float*)d_in[2];
    const float* w_proj = (const float*)d_in[3];
    const float* b_proj = (const float*)d_in[4];
    float* out = (float*)d_out;

    cudaFuncSetAttribute(gemm_mma<0>, cudaFuncAttributeMaxDynamicSharedMemorySize, SMEM_BYTES);
    cudaFuncSetAttribute(gemm_mma<1>, cudaFuncAttributeMaxDynamicSharedMemorySize, SMEM_BYTES);

    split_k<0><<<(ROWS * EMBED / 8 + 255) / 256, 256>>>(x,      ROWS * EMBED / 8);
    split_k<1><<<(QKV_N * EMBED / 8 + 255) / 256, 256>>>(w_qkv, QKV_N * EMBED / 8);
    split_k<2><<<(EMBED * EMBED / 8 + 255) / 256, 256>>>(w_proj, EMBED * EMBED / 8);

    gemm_mma<0><<<dim3(QKV_N / 128, ROWS / 128), 256, SMEM_BYTES>>>(b_qkv, nullptr);
    attn_kernel<<<dim3(BATCH * HEADS, SEQ / 128), 128>>>();
    gemm_mma<1><<<dim3(EMBED / 128, ROWS / 128), 256, SMEM_BYTES>>>(b_proj, out);
}

// round 4
// speedup vs baseline: 5.2461x; 2.6442x over previous
#include <cuda_runtime.h>
#include <cuda_bf16.h>
#include <cstdint>

#define EMBED   1024
#define HEADS   16
#define HD      64
#define BATCH   8
#define SEQ     1024
#define ROWS    8192
#define QKV_N   3072
#define KDIM    1024
#define LOG2E   1.4426950408889634f
#define QSCALE  (0.125f * LOG2E)          // fold 1/sqrt(64) and log2(e) into Q

// ---------------- scratch (device globals; allocation-free) ----------------
__device__ __align__(1024) __nv_bfloat16 g_xh[ROWS * EMBED];
__device__ __align__(1024) __nv_bfloat16 g_xl[ROWS * EMBED];
__device__ __align__(1024) __nv_bfloat16 g_wqh[QKV_N * EMBED];
__device__ __align__(1024) __nv_bfloat16 g_wql[QKV_N * EMBED];
__device__ __align__(1024) __nv_bfloat16 g_wph[EMBED * EMBED];
__device__ __align__(1024) __nv_bfloat16 g_wpl[EMBED * EMBED];
// Q/K/V as bf16 hi/lo, layout [B,H,N,D]; Q pre-scaled by QSCALE
__device__ __align__(1024) __nv_bfloat16 g_qh[BATCH * HEADS * SEQ * HD];
__device__ __align__(1024) __nv_bfloat16 g_ql[BATCH * HEADS * SEQ * HD];
__device__ __align__(1024) __nv_bfloat16 g_kh[BATCH * HEADS * SEQ * HD];
__device__ __align__(1024) __nv_bfloat16 g_kl[BATCH * HEADS * SEQ * HD];
__device__ __align__(1024) __nv_bfloat16 g_vh[BATCH * HEADS * SEQ * HD];
__device__ __align__(1024) __nv_bfloat16 g_vl[BATCH * HEADS * SEQ * HD];
__device__ __align__(1024) __nv_bfloat16 g_ah[ROWS * EMBED];      // attention out hi
__device__ __align__(1024) __nv_bfloat16 g_al[ROWS * EMBED];      // attention out lo

// ---------------- helpers ----------------
__device__ __forceinline__ uint32_t smem_u32(const void* p) {
    uint32_t a;
    asm("{ .reg .u64 t; cvta.to.shared.u64 t, %1; cvt.u32.u64 %0, t; }" : "=r"(a) : "l"(p));
    return a;
}
__device__ __forceinline__ float ex2f(float x) {
    float y; asm("ex2.approx.ftz.f32 %0, %1;" : "=f"(y) : "f"(x)); return y;
}
__device__ __forceinline__ uint32_t sw128(uint32_t o) { return o ^ ((o >> 3) & 0x70); }

#define CP_ASYNC(dst, src) \
    asm volatile("cp.async.cg.shared.global [%0], [%1], 16;" :: "r"(dst), "l"(src) : "memory")
#define CP_COMMIT() asm volatile("cp.async.commit_group;" ::: "memory")
#define CP_WAIT1()  asm volatile("cp.async.wait_group 1;" ::: "memory")
#define CP_WAIT0()  asm volatile("cp.async.wait_group 0;" ::: "memory")

__device__ __forceinline__ void ldsm4(uint32_t r[4], uint32_t addr) {
    asm volatile("ldmatrix.sync.aligned.m8n8.x4.shared.b16 {%0,%1,%2,%3}, [%4];"
                 : "=r"(r[0]), "=r"(r[1]), "=r"(r[2]), "=r"(r[3]) : "r"(addr));
}
__device__ __forceinline__ void ldsm4t(uint32_t r[4], uint32_t addr) {
    asm volatile("ldmatrix.sync.aligned.m8n8.x4.trans.shared.b16 {%0,%1,%2,%3}, [%4];"
                 : "=r"(r[0]), "=r"(r[1]), "=r"(r[2]), "=r"(r[3]) : "r"(addr));
}
__device__ __forceinline__ void mma_bf16(float c[4], const uint32_t a[4],
                                         uint32_t b0, uint32_t b1) {
    asm volatile(
        "mma.sync.aligned.m16n8k16.row.col.f32.bf16.bf16.f32 "
        "{%0,%1,%2,%3}, {%4,%5,%6,%7}, {%8,%9}, {%0,%1,%2,%3};"
        : "+f"(c[0]), "+f"(c[1]), "+f"(c[2]), "+f"(c[3])
        : "r"(a[0]), "r"(a[1]), "r"(a[2]), "r"(a[3]), "r"(b0), "r"(b1));
}

// split (v0,v1) -> packed bf16x2 hi + residual lo (v0 in low half)
__device__ __forceinline__ void split2(float v0, float v1, uint32_t& hi, uint32_t& lo) {
    __nv_bfloat162 h2 = __floats2bfloat162_rn(v0, v1);
    float2 hf = __bfloat1622float2(h2);
    __nv_bfloat162 l2 = __floats2bfloat162_rn(v0 - hf.x, v1 - hf.y);
    hi = *reinterpret_cast<uint32_t*>(&h2);
    lo = *reinterpret_cast<uint32_t*>(&l2);
}

// ---------------- fp32 -> bf16 hi/lo split (inputs) ----------------
template <int T>
__global__ __launch_bounds__(256)
void split_k(const float* __restrict__ src, int n8)
{
    __nv_bfloat16* h = (T == 0) ? g_xh : (T == 1) ? g_wqh : g_wph;
    __nv_bfloat16* l = (T == 0) ? g_xl : (T == 1) ? g_wql : g_wpl;
    int i = blockIdx.x * 256 + threadIdx.x;
    if (i >= n8) return;
    float4 a = ((const float4*)src)[i * 2];
    float4 b = ((const float4*)src)[i * 2 + 1];
    float v[8] = {a.x, a.y, a.z, a.w, b.x, b.y, b.z, b.w};
    __nv_bfloat16 hb[8], lb[8];
#pragma unroll
    for (int j = 0; j < 8; j++) {
        hb[j] = __float2bfloat16(v[j]);
        lb[j] = __float2bfloat16(v[j] - __bfloat162float(hb[j]));
    }
    ((uint4*)h)[i] = *(uint4*)hb;
    ((uint4*)l)[i] = *(uint4*)lb;
}

// ---------------- mma.sync split-bf16 GEMM: C = A @ B^T + bias ----------------
#define STG_BYTES 65536            // Ah,Al,Bh,Bl = 4 x 16KB per stage
#define SMEM_BYTES (2 * STG_BYTES)

template <int MODE>
__global__ __launch_bounds__(256)
void gemm_mma(const float* __restrict__ bias, float* __restrict__ Cout)
{
    extern __shared__ char smem[];
    const uint32_t sb = smem_u32(smem);
    const int tid = threadIdx.x;
    const int lane = tid & 31;
    const int wid  = tid >> 5;
    const int warp_m = wid & 3;
    const int warp_n = wid >> 2;
    const int m0 = blockIdx.y * 128;
    const int n0 = blockIdx.x * 128;

    const __nv_bfloat16* Ah = (MODE == 0) ? g_xh  : g_ah;
    const __nv_bfloat16* Al = (MODE == 0) ? g_xl  : g_al;
    const __nv_bfloat16* Bh = (MODE == 0) ? g_wqh : g_wph;
    const __nv_bfloat16* Bl = (MODE == 0) ? g_wql : g_wpl;

    const int r0  = tid >> 3;
    const int seg = tid & 7;

    auto issue = [&](int stage, int kt) {
        const uint32_t s0 = sb + stage * STG_BYTES;
#pragma unroll
        for (int u = 0; u < 4; u++) {
            const int row = r0 + u * 32;
            const uint32_t so = sw128((uint32_t)(row * 128 + seg * 16));
            const int ae = (m0 + row) * KDIM + kt + seg * 8;
            const int be = (n0 + row) * KDIM + kt + seg * 8;
            CP_ASYNC(s0 +         so, (const char*)(Ah + ae));
            CP_ASYNC(s0 + 16384 + so, (const char*)(Al + ae));
            CP_ASYNC(s0 + 32768 + so, (const char*)(Bh + be));
            CP_ASYNC(s0 + 49152 + so, (const char*)(Bl + be));
        }
    };

    float c[2][8][4];
#pragma unroll
    for (int mt = 0; mt < 2; mt++)
#pragma unroll
        for (int nt = 0; nt < 8; nt++)
#pragma unroll
            for (int j = 0; j < 4; j++) c[mt][nt][j] = 0.f;

    issue(0, 0);
    CP_COMMIT();

    const int NIT = KDIM / 64;
    for (int it = 0; it < NIT; it++) {
        const int s = it & 1;
        if (it + 1 < NIT) { issue(s ^ 1, (it + 1) * 64); CP_COMMIT(); CP_WAIT1(); }
        else              { CP_WAIT0(); }
        __syncthreads();

        const uint32_t sA_h = sb + s * STG_BYTES;
        const uint32_t sA_l = sA_h + 16384;
        const uint32_t sB_h = sA_h + 32768;
        const uint32_t sB_l = sA_h + 49152;

#pragma unroll
        for (int ks = 0; ks < 4; ks++) {
            uint32_t ah[2][4], al[2][4];
#pragma unroll
            for (int mt = 0; mt < 2; mt++) {
                const int arow = warp_m * 32 + mt * 16 + (lane & 7) + ((lane >> 3) & 1) * 8;
                const int aseg = ks * 2 + (lane >> 4);
                const uint32_t off = sw128((uint32_t)(arow * 128 + aseg * 16));
                ldsm4(ah[mt], sA_h + off);
                ldsm4(al[mt], sA_l + off);
            }
            uint32_t bh[8][2], bl[8][2];
#pragma unroll
            for (int p = 0; p < 4; p++) {
                const int brow = warp_n * 64 + p * 16 + (lane >> 4) * 8 + (lane & 7);
                const int bseg = ks * 2 + ((lane >> 3) & 1);
                const uint32_t off = sw128((uint32_t)(brow * 128 + bseg * 16));
                uint32_t rh[4], rl[4];
                ldsm4(rh, sB_h + off);
                ldsm4(rl, sB_l + off);
                bh[2*p][0] = rh[0]; bh[2*p][1] = rh[1];
                bh[2*p+1][0] = rh[2]; bh[2*p+1][1] = rh[3];
                bl[2*p][0] = rl[0]; bl[2*p][1] = rl[1];
                bl[2*p+1][0] = rl[2]; bl[2*p+1][1] = rl[3];
            }
#pragma unroll
            for (int mt = 0; mt < 2; mt++)
#pragma unroll
                for (int nt = 0; nt < 8; nt++) {
                    mma_bf16(c[mt][nt], ah[mt], bh[nt][0], bh[nt][1]);
                    mma_bf16(c[mt][nt], ah[mt], bl[nt][0], bl[nt][1]);
                    mma_bf16(c[mt][nt], al[mt], bh[nt][0], bh[nt][1]);
                }
        }
        __syncthreads();
    }

    const int g = lane >> 2, t = lane & 3;
#pragma unroll
    for (int mt = 0; mt < 2; mt++) {
#pragma unroll
        for (int nt = 0; nt < 8; nt++) {
            const int col = n0 + warp_n * 64 + nt * 8 + t * 2;
            const float b0 = __ldg(&bias[col]), b1 = __ldg(&bias[col + 1]);
#pragma unroll
            for (int half = 0; half < 2; half++) {
                const int row = m0 + warp_m * 32 + mt * 16 + g + half * 8;
                float v0 = c[mt][nt][half * 2 + 0] + b0;
                float v1 = c[mt][nt][half * 2 + 1] + b1;
                if (MODE == 0) {
                    const int b_ = row >> 10, n = row & 1023;
                    const int ty = col >> 10, rem = col & 1023;
                    const int h  = rem >> 6, d = rem & 63;
                    if (ty == 0) { v0 *= QSCALE; v1 *= QSCALE; }
                    const int idx = (((b_ * HEADS + h) * SEQ) + n) * HD + d;
                    uint32_t hi, lo;
                    split2(v0, v1, hi, lo);
                    __nv_bfloat16* dh = (ty == 0) ? g_qh : (ty == 1) ? g_kh : g_vh;
                    __nv_bfloat16* dl = (ty == 0) ? g_ql : (ty == 1) ? g_kl : g_vl;
                    *(uint32_t*)(dh + idx) = hi;
                    *(uint32_t*)(dl + idx) = lo;
                } else {
                    *(float2*)(Cout + row * EMBED + col) = make_float2(v0, v1);
                }
            }
        }
    }
}

// ---------------- tensor-core flash attention ----------------
// grid (B*H, SEQ/128), 256 threads / 8 warps; warp w owns q rows w*16..w*16+15.
// smem: Qh 16K | Ql 16K | 2 stages x (Kh 8K | Kl 8K | Vh 8K | Vl 8K)
#define ATTN_SMEM 98304
#define NKT (SEQ / 64)

__global__ __launch_bounds__(256, 1)
void attn_tc()
{
    extern __shared__ char smem[];
    const uint32_t sb = smem_u32(smem);
    const int tid = threadIdx.x, lane = tid & 31, w = tid >> 5;
    const int bh = blockIdx.x, qt = blockIdx.y;
    const int g = lane >> 2, t = lane & 3;

    const uint32_t SQH = sb, SQL = sb + 16384;

    auto issueQ = [&]() {
        const int row0 = tid >> 3, seg = tid & 7;
#pragma unroll
        for (int u = 0; u < 4; u++) {
            const int row = row0 + u * 32;
            const uint32_t off = sw128((uint32_t)(row * 128 + seg * 16));
            const int e = ((bh * SEQ) + qt * 128 + row) * HD + seg * 8;
            CP_ASYNC(SQH + off, (const char*)(g_qh + e));
            CP_ASYNC(SQL + off, (const char*)(g_ql + e));
        }
    };
    auto issueKV = [&](int s, int kt) {
        const uint32_t base = sb + 32768 + s * 32768;
        const int row0 = tid >> 3, seg = tid & 7;
#pragma unroll
        for (int u = 0; u < 2; u++) {
            const int row = row0 + u * 32;
            const uint32_t off = sw128((uint32_t)(row * 128 + seg * 16));
            const int e = ((bh * SEQ) + kt + row) * HD + seg * 8;
            CP_ASYNC(base +         off, (const char*)(g_kh + e));
            CP_ASYNC(base +  8192 + off, (const char*)(g_kl + e));
            CP_ASYNC(base + 16384 + off, (const char*)(g_vh + e));
            CP_ASYNC(base + 24576 + off, (const char*)(g_vl + e));
        }
    };

    issueQ(); issueKV(0, 0); CP_COMMIT();
    issueKV(1, 64); CP_COMMIT();
    CP_WAIT1(); __syncthreads();

    // Q fragments, held for whole kernel
    uint32_t qh[4][4], ql[4][4];
    {
        const int arow = w * 16 + (lane & 7) + ((lane >> 3) & 1) * 8;
#pragma unroll
        for (int ks = 0; ks < 4; ks++) {
            const uint32_t off = sw128((uint32_t)(arow * 128 + (ks * 2 + (lane >> 4)) * 16));
            ldsm4(qh[ks], SQH + off);
            ldsm4(ql[ks], SQL + off);
        }
    }

    float o[8][4];
#pragma unroll
    for (int nt = 0; nt < 8; nt++)
#pragma unroll
        for (int j = 0; j < 4; j++) o[nt][j] = 0.f;
    float m0 = -1e30f, m1 = -1e30f, l0 = 0.f, l1 = 0.f;

    for (int it = 0; it < NKT; it++) {
        if (it > 0) {
            if (it + 1 < NKT) CP_WAIT1(); else CP_WAIT0();
            __syncthreads();
        }
        const uint32_t KH = sb + 32768 + (it & 1) * 32768;
        const uint32_t KL = KH + 8192, VH = KH + 16384, VL = KH + 24576;

        // ---- S = Q @ K^T (3-pass split) ----
        float c[8][4];
#pragma unroll
        for (int nt = 0; nt < 8; nt++)
#pragma unroll
            for (int j = 0; j < 4; j++) c[nt][j] = 0.f;

#pragma unroll
        for (int ks = 0; ks < 4; ks++) {
            uint32_t kh[4][4], kl[4][4];
#pragma unroll
            for (int p = 0; p < 4; p++) {
                const int brow = p * 16 + (lane >> 4) * 8 + (lane & 7);
                const uint32_t off =
                    sw128((uint32_t)(brow * 128 + (ks * 2 + ((lane >> 3) & 1)) * 16));
                ldsm4(kh[p], KH + off);
                ldsm4(kl[p], KL + off);
            }
#pragma unroll
            for (int p = 0; p < 4; p++) {
                mma_bf16(c[2*p],   qh[ks], kh[p][0], kh[p][1]);
                mma_bf16(c[2*p],   qh[ks], kl[p][0], kl[p][1]);
                mma_bf16(c[2*p],   ql[ks], kh[p][0], kh[p][1]);
                mma_bf16(c[2*p+1], qh[ks], kh[p][2], kh[p][3]);
                mma_bf16(c[2*p+1], qh[ks], kl[p][2], kl[p][3]);
                mma_bf16(c[2*p+1], ql[ks], kh[p][2], kh[p][3]);
            }
        }

        // ---- online softmax (rows g and g+8; S already in log2 domain) ----
        float mx0 = -1e30f, mx1 = -1e30f;
#pragma unroll
        for (int nt = 0; nt < 8; nt++) {
            mx0 = fmaxf(mx0, fmaxf(c[nt][0], c[nt][1]));
            mx1 = fmaxf(mx1, fmaxf(c[nt][2], c[nt][3]));
        }
        mx0 = fmaxf(mx0, __shfl_xor_sync(0xffffffffu, mx0, 1));
        mx0 = fmaxf(mx0, __shfl_xor_sync(0xffffffffu, mx0, 2));
        mx1 = fmaxf(mx1, __shfl_xor_sync(0xffffffffu, mx1, 1));
        mx1 = fmaxf(mx1, __shfl_xor_sync(0xffffffffu, mx1, 2));
        const float mn0 = fmaxf(m0, mx0), mn1 = fmaxf(m1, mx1);
        const float cor0 = ex2f(m0 - mn0), cor1 = ex2f(m1 - mn1);
        m0 = mn0; m1 = mn1;
        float s0 = 0.f, s1 = 0.f;
#pragma unroll
        for (int nt = 0; nt < 8; nt++) {
            c[nt][0] = ex2f(c[nt][0] - m0);
            c[nt][1] = ex2f(c[nt][1] - m0);
            c[nt][2] = ex2f(c[nt][2] - m1);
            c[nt][3] = ex2f(c[nt][3] - m1);
            s0 += c[nt][0] + c[nt][1];
            s1 += c[nt][2] + c[nt][3];
            o[nt][0] *= cor0; o[nt][1] *= cor0;
            o[nt][2] *= cor1; o[nt][3] *= cor1;
        }
        s0 += __shfl_xor_sync(0xffffffffu, s0, 1);
        s0 += __shfl_xor_sync(0xffffffffu, s0, 2);
        s1 += __shfl_xor_sync(0xffffffffu, s1, 1);
        s1 += __shfl_xor_sync(0xffffffffu, s1, 2);
        l0 = l0 * cor0 + s0;
        l1 = l1 * cor1 + s1;

        // ---- O += P @ V (3-pass split; P frags from accum regs) ----
#pragma unroll
        for (int ks = 0; ks < 4; ks++) {
            uint32_t ph[4], pl[4];
            split2(c[2*ks][0],   c[2*ks][1],   ph[0], pl[0]);
            split2(c[2*ks][2],   c[2*ks][3],   ph[1], pl[1]);
            split2(c[2*ks+1][0], c[2*ks+1][1], ph[2], pl[2]);
            split2(c[2*ks+1][2], c[2*ks+1][3], ph[3], pl[3]);

            uint32_t vh[4][4], vl[4][4];
#pragma unroll
            for (int p = 0; p < 4; p++) {
                const int krow = ks * 16 + (lane & 15);
                const int ncol = p * 16 + (lane >> 4) * 8;
                const uint32_t off = sw128((uint32_t)(krow * 128 + ncol * 2));
                ldsm4t(vh[p], VH + off);
                ldsm4t(vl[p], VL + off);
            }
#pragma unroll
            for (int p = 0; p < 4; p++) {
                mma_bf16(o[2*p],   ph, vh[p][0], vh[p][1]);
                mma_bf16(o[2*p],   pl, vh[p][0], vh[p][1]);
                mma_bf16(o[2*p],   ph, vl[p][0], vl[p][1]);
                mma_bf16(o[2*p+1], ph, vh[p][2], vh[p][3]);
                mma_bf16(o[2*p+1], pl, vh[p][2], vh[p][3]);
                mma_bf16(o[2*p+1], ph, vl[p][2], vl[p][3]);
            }
        }
        __syncthreads();
        if (it + 2 < NKT) { issueKV(it & 1, (it + 2) * 64); CP_COMMIT(); }
    }

    // ---- epilogue: normalize, hi/lo split, write [row, E] ----
    const float i0 = 1.f / l0, i1 = 1.f / l1;
    const int b_ = bh >> 4, h = bh & 15;
    const int r0 = b_ * SEQ + qt * 128 + w * 16 + g;
#pragma unroll
    for (int nt = 0; nt < 8; nt++) {
        const int col = h * HD + nt * 8 + t * 2;
        uint32_t hi, lo;
        split2(o[nt][0] * i0, o[nt][1] * i0, hi, lo);
        *(uint32_t*)(g_ah + r0 * EMBED + col) = hi;
        *(uint32_t*)(g_al + r0 * EMBED + col) = lo;
        split2(o[nt][2] * i1, o[nt][3] * i1, hi, lo);
        *(uint32_t*)(g_ah + (r0 + 8) * EMBED + col) = hi;
        *(uint32_t*)(g_al + (r0 + 8) * EMBED + col) = lo;
    }
}

// ---------------------------------------------------------------------------
extern "C" void kernel_launch(void* const* d_in, const int* in_sizes, int n_in,
                              void* d_out, int out_size)
{
    (void)in_sizes; (void)n_in; (void)out_size;
    const float* x      = (const float*)d_in[0];
    const float* w_qkv  = (const float*)d_in[1];
    const float* b_qkv  = (const float*)d_in[2];
    const float* w_proj = (const float*)d_in[3];
    const float* b_proj = (const float*)d_in[4];
    float* out = (float*)d_out;

    cudaFuncSetAttribute(gemm_mma<0>, cudaFuncAttributeMaxDynamicSharedMemorySize, SMEM_BYTES);
    cudaFuncSetAttribute(gemm_mma<1>, cudaFuncAttributeMaxDynamicSharedMemorySize, SMEM_BYTES);
    cudaFuncSetAttribute(attn_tc, cudaFuncAttributeMaxDynamicSharedMemorySize, ATTN_SMEM);

    split_k<0><<<(ROWS * EMBED / 8 + 255) / 256, 256>>>(x,      ROWS * EMBED / 8);
    split_k<1><<<(QKV_N * EMBED / 8 + 255) / 256, 256>>>(w_qkv, QKV_N * EMBED / 8);
    split_k<2><<<(EMBED * EMBED / 8 + 255) / 256, 256>>>(w_proj, EMBED * EMBED / 8);

    gemm_mma<0><<<dim3(QKV_N / 128, ROWS / 128), 256, SMEM_BYTES>>>(b_qkv, nullptr);
    attn_tc<<<dim3(BATCH * HEADS, SEQ / 128), 256, ATTN_SMEM>>>();
    gemm_mma<1><<<dim3(EMBED / 128, ROWS / 128), 256, SMEM_BYTES>>>(b_proj, out);
}